// round 16
// baseline (speedup 1.0000x reference)
#include <cuda_runtime.h>
#include <cuda_fp16.h>
#include <cstdint>
#include <cstddef>

#define KDIM 4096
#define NDIM 4096
#define BDIM 8192
#define NG   32

// Scratch: rotated+scaled fp16 weights (32MB), fp16 X (64MB), k-major Pi (2MB).
__device__ __half g_Wh[(size_t)NDIM * KDIM];
__device__ __half g_Xh[(size_t)BDIM * KDIM];
__device__ float  g_PiT[(size_t)NG * 128 * 128];

// ---------------------------------------------------------------------------
// Kernel 0: convert X to fp16.
// ---------------------------------------------------------------------------
__global__ void xhalf(const float4* __restrict__ x) {
    const size_t i = (size_t)blockIdx.x * blockDim.x + threadIdx.x;  // < B*K/4
    const float4 v = x[i];
    __half2 h01 = __floats2half2_rn(v.x, v.y);
    __half2 h23 = __floats2half2_rn(v.z, v.w);
    uint2 o;
    o.x = *(uint32_t*)&h01;
    o.y = *(uint32_t*)&h23;
    ((uint2*)g_Xh)[i] = o;
}

// ---------------------------------------------------------------------------
// Kernel 0b: PiT[g][k][j] = rot[g][j][k] (full fp32). One 32x32 tile per block.
// ---------------------------------------------------------------------------
__global__ void pit(const float* __restrict__ rot) {
    __shared__ float t[32][33];
    const int g = blockIdx.z;
    const int j0 = blockIdx.x * 32, k0 = blockIdx.y * 32;
    const int x = threadIdx.x, y = threadIdx.y;  // 32 x 8
    const float* src = rot + (size_t)g * 16384;
    float* dst = g_PiT + (size_t)g * 16384;
#pragma unroll
    for (int i = 0; i < 4; ++i)
        t[y + i * 8][x] = src[(j0 + y + i * 8) * 128 + k0 + x];
    __syncthreads();
#pragma unroll
    for (int i = 0; i < 4; ++i)
        dst[(size_t)(k0 + y + i * 8) * 128 + j0 + x] = t[x][y + i * 8];
}

// ---------------------------------------------------------------------------
// Kernel 1: dequant + rotate + scale -> fp16, fma.rn.f32x2 inner product,
// index gather for iteration c+1 prefetched into registers during c's FMAs.
// ---------------------------------------------------------------------------
#define SST 132
#define ROT_SMEM ((128 * SST + 8 * SST) * 4)   // 69696 B

static __device__ __forceinline__ void ffma2(uint64_t& d, uint64_t a, uint64_t b) {
    asm("fma.rn.f32x2 %0, %1, %2, %0;" : "+l"(d) : "l"(a), "l"(b));
}

__global__ __launch_bounds__(256) void rotate_weights(const int* __restrict__ indices,
                                                      const float* __restrict__ codebook,
                                                      const float* __restrict__ norms) {
    extern __shared__ float sm[];
    float* PiK = sm;               // 128 x SST (k-major Pi rows)
    float* Wl = sm + 128 * SST;    // 8 x SST
    __shared__ float cb[16];
    __shared__ float nmv[64];
    const int g = blockIdx.x;
    const int nblk = blockIdx.y * 64;
    const int tid = threadIdx.x;
    if (tid < 16) cb[tid] = codebook[tid];
    if (tid < 64) nmv[tid] = norms[(nblk + tid) * NG + g] * 0.088388347648318447f;
    // Fill PiK from k-major g_PiT, coalesced.
    const float4* Pg = (const float4*)(g_PiT + (size_t)g * 16384);
#pragma unroll
    for (int p = 0; p < 16; ++p) {
        const int flat = p * 256 + tid;   // 0..4095
        const int k = flat >> 5;
        const int q = flat & 31;
        *(float4*)(PiK + k * SST + q * 4) = Pg[flat];
    }
    const int kcol = tid & 127;
    const int rh = tid >> 7;
    const int dr = (tid * 4) >> 7;     // dequant row 0..7
    const int dj = (tid * 4) & 127;    // dequant col
    const int* ip = indices + (size_t)(nblk + dr) * KDIM + g * 128 + dj;

    int4 iv = *(const int4*)ip;        // prefetch c = 0
    __syncthreads();

    for (int c = 0; c < 8; ++c) {
        {   // dequant 8 rows x 128 from prefetched iv
            const float nm = nmv[c * 8 + dr];
            float4 o;
            o.x = cb[iv.x] * nm;
            o.y = cb[iv.y] * nm;
            o.z = cb[iv.z] * nm;
            o.w = cb[iv.w] * nm;
            *(float4*)(Wl + dr * SST + dj) = o;
        }
        __syncthreads();
        // Issue next iteration's gather early; completes under the FMA loop.
        int4 ivn = make_int4(0, 0, 0, 0);
        if (c < 7) ivn = *(const int4*)(ip + (size_t)(c + 1) * 8 * KDIM);

        uint64_t acc0 = 0ull, acc1 = 0ull, acc2 = 0ull, acc3 = 0ull;
        const float* pk = PiK + kcol * SST;
        const float* w0 = Wl + (rh * 4 + 0) * SST;
        const float* w1 = Wl + (rh * 4 + 1) * SST;
        const float* w2 = Wl + (rh * 4 + 2) * SST;
        const float* w3 = Wl + (rh * 4 + 3) * SST;
#pragma unroll
        for (int j4 = 0; j4 < 32; ++j4) {
            const ulonglong2 p2 = *(const ulonglong2*)(pk + j4 * 4);
            ulonglong2 v;
            v = *(const ulonglong2*)(w0 + j4 * 4); ffma2(acc0, p2.x, v.x); ffma2(acc0, p2.y, v.y);
            v = *(const ulonglong2*)(w1 + j4 * 4); ffma2(acc1, p2.x, v.x); ffma2(acc1, p2.y, v.y);
            v = *(const ulonglong2*)(w2 + j4 * 4); ffma2(acc2, p2.x, v.x); ffma2(acc2, p2.y, v.y);
            v = *(const ulonglong2*)(w3 + j4 * 4); ffma2(acc3, p2.x, v.x); ffma2(acc3, p2.y, v.y);
        }
        __syncthreads();
        const size_t base = (size_t)(nblk + c * 8 + rh * 4) * KDIM + g * 128 + kcol;
        float2 f0 = *(float2*)&acc0, f1 = *(float2*)&acc1;
        float2 f2 = *(float2*)&acc2, f3 = *(float2*)&acc3;
        g_Wh[base + 0 * (size_t)KDIM] = __float2half_rn(f0.x + f0.y);
        g_Wh[base + 1 * (size_t)KDIM] = __float2half_rn(f1.x + f1.y);
        g_Wh[base + 2 * (size_t)KDIM] = __float2half_rn(f2.x + f2.y);
        g_Wh[base + 3 * (size_t)KDIM] = __float2half_rn(f3.x + f3.y);
        iv = ivn;
    }
}

// ---------------------------------------------------------------------------
// Kernel 2: out(8192x4096) = Xh @ Wh^T, fp16 mma.sync m16n8k16, fp32 acc.
// CTA 128x128, BK=64 halves, 3-stage cp.async, 8 warps (2x4), warp tile 64x32.
// (Exact R11/R13 kernel — best measured config.)
// ---------------------------------------------------------------------------
#define BM 128
#define BN 128
#define BK 64
#define STAGES 3
#define SSTRH 72                       // halves per row (144B)
#define A_H (BM * SSTRH)               // 9216 halves (18432B)
#define STG_B (2 * A_H * 2)            // 36864 bytes per stage (A+B)
#define GEMM_SMEM (STAGES * STG_B)     // 110592 B

static __device__ __forceinline__ void cp16(uint32_t dst, const void* src) {
    asm volatile("cp.async.cg.shared.global [%0], [%1], 16;\n" :: "r"(dst), "l"(src));
}

static __device__ __forceinline__ void ldm4(uint32_t* r, uint32_t addr) {
    asm volatile("ldmatrix.sync.aligned.m8n8.x4.shared.b16 {%0,%1,%2,%3}, [%4];"
                 : "=r"(r[0]), "=r"(r[1]), "=r"(r[2]), "=r"(r[3]) : "r"(addr));
}

static __device__ __forceinline__ void mma_f16(float* d, const uint32_t* a, const uint32_t* b) {
    asm volatile(
        "mma.sync.aligned.m16n8k16.row.col.f32.f16.f16.f32 "
        "{%0,%1,%2,%3}, {%4,%5,%6,%7}, {%8,%9}, {%0,%1,%2,%3};\n"
        : "+f"(d[0]), "+f"(d[1]), "+f"(d[2]), "+f"(d[3])
        : "r"(a[0]), "r"(a[1]), "r"(a[2]), "r"(a[3]), "r"(b[0]), "r"(b[1]));
}

static __device__ __forceinline__ void copy_stage(uint32_t sAu, int s,
                                                  const __half* __restrict__ Xh,
                                                  const __half* __restrict__ Wh,
                                                  int bm, int bn, int kt, int tid) {
    const int k0 = kt * BK;
    const uint32_t sbase = sAu + (uint32_t)(s * STG_B);
#pragma unroll
    for (int p = 0; p < 4; ++p) {
        const int a = p * 256 + tid;
        const int row = a >> 3;
        const int ck = a & 7;
        cp16(sbase + (uint32_t)(row * (SSTRH * 2) + ck * 16),
             Xh + (size_t)(bm + row) * KDIM + k0 + ck * 8);
    }
    const uint32_t bbase = sbase + (uint32_t)(A_H * 2);
#pragma unroll
    for (int p = 0; p < 4; ++p) {
        const int a = p * 256 + tid;
        const int row = a >> 3;
        const int ck = a & 7;
        cp16(bbase + (uint32_t)(row * (SSTRH * 2) + ck * 16),
             Wh + (size_t)(bn + row) * KDIM + k0 + ck * 8);
    }
}

__global__ __launch_bounds__(256, 2) void gemm_f16(float* __restrict__ out) {
    extern __shared__ __half smh[];
    const int tid = threadIdx.x;
    const int warp = tid >> 5, lane = tid & 31;
    const int wm = (warp >> 2) * 64, wn = (warp & 3) * 32;
    const int bm = blockIdx.y * BM, bn = blockIdx.x * BN;
    const __half* Xh = g_Xh;
    const __half* Wh = g_Wh;
    const uint32_t sAu = (uint32_t)__cvta_generic_to_shared(smh);

    float acc[4][4][4];
#pragma unroll
    for (int i = 0; i < 4; ++i)
#pragma unroll
        for (int j = 0; j < 4; ++j)
#pragma unroll
            for (int r = 0; r < 4; ++r) acc[i][j][r] = 0.f;

    const uint32_t aoff =
        (uint32_t)((((lane >> 3) & 1) * 8 + (lane & 7)) * 144 + (lane >> 4) * 16);
    const uint32_t boff =
        (uint32_t)(((lane >> 4) * 8 + (lane & 7)) * 144 + ((lane >> 3) & 1) * 16);

#pragma unroll
    for (int s = 0; s < STAGES - 1; ++s) {
        copy_stage(sAu, s, Xh, Wh, bm, bn, s, tid);
        asm volatile("cp.async.commit_group;\n");
    }
    asm volatile("cp.async.wait_group %0;\n" :: "n"(STAGES - 2));
    __syncthreads();

    const int lr = lane >> 2;
    const int lc = lane & 3;
    const int KT = KDIM / BK;  // 64
    int s_rd = 0, s_wr = STAGES - 1;

#pragma unroll 1
    for (int kt = 0; kt < KT; ++kt) {
        if (kt + STAGES - 1 < KT) {
            copy_stage(sAu, s_wr, Xh, Wh, bm, bn, kt + STAGES - 1, tid);
        }
        asm volatile("cp.async.commit_group;\n");

        const uint32_t At = sAu + (uint32_t)(s_rd * STG_B) + (uint32_t)(wm * 144) + aoff;
        const uint32_t Bt = sAu + (uint32_t)(s_rd * STG_B + A_H * 2) +
                            (uint32_t)(wn * 144) + boff;

#pragma unroll
        for (int ks = 0; ks < 4; ++ks) {
            uint32_t af[4][4], bf[4][2];
#pragma unroll
            for (int mt = 0; mt < 4; ++mt)
                ldm4(af[mt], At + (uint32_t)(mt * 16 * 144 + ks * 32));
#pragma unroll
            for (int np = 0; np < 2; ++np) {
                uint32_t r[4];
                ldm4(r, Bt + (uint32_t)(np * 16 * 144 + ks * 32));
                bf[np * 2][0] = r[0];
                bf[np * 2][1] = r[1];
                bf[np * 2 + 1][0] = r[2];
                bf[np * 2 + 1][1] = r[3];
            }
#pragma unroll
            for (int mt = 0; mt < 4; ++mt)
#pragma unroll
                for (int nt = 0; nt < 4; ++nt)
                    mma_f16(acc[mt][nt], af[mt], bf[nt]);
        }

        asm volatile("cp.async.wait_group %0;\n" :: "n"(STAGES - 2));
        __syncthreads();
        s_rd = (s_rd == STAGES - 1) ? 0 : s_rd + 1;
        s_wr = (s_wr == STAGES - 1) ? 0 : s_wr + 1;
    }

#pragma unroll
    for (int mt = 0; mt < 4; ++mt) {
#pragma unroll
        for (int nt = 0; nt < 4; ++nt) {
            const int row = bm + wm + mt * 16 + lr;
            const int col = bn + wn + nt * 8 + lc * 2;
            float2 v0 = make_float2(acc[mt][nt][0], acc[mt][nt][1]);
            float2 v1 = make_float2(acc[mt][nt][2], acc[mt][nt][3]);
            *(float2*)(out + (size_t)row * NDIM + col) = v0;
            *(float2*)(out + (size_t)(row + 8) * NDIM + col) = v1;
        }
    }
}

// ---------------------------------------------------------------------------
extern "C" void kernel_launch(void* const* d_in, const int* in_sizes, int n_in,
                              void* d_out, int out_size) {
    const float* x        = (const float*)d_in[0];   // (8192, 4096) f32
    const int*   indices  = (const int*)d_in[1];     // (4096, 4096) i32
    const float* codebook = (const float*)d_in[2];   // (16,) f32
    const float* norms    = (const float*)d_in[3];   // (4096, 32) f32
    const float* rot      = (const float*)d_in[4];   // (32, 128, 128) f32
    float* out = (float*)d_out;                      // (8192, 4096) f32

    cudaFuncSetAttribute(rotate_weights, cudaFuncAttributeMaxDynamicSharedMemorySize, ROT_SMEM);
    cudaFuncSetAttribute(gemm_f16, cudaFuncAttributeMaxDynamicSharedMemorySize, GEMM_SMEM);

    xhalf<<<(BDIM * KDIM / 4) / 256, 256>>>((const float4*)x);
    pit<<<dim3(4, 4, NG), dim3(32, 8)>>>(rot);
    rotate_weights<<<dim3(NG, NDIM / 64), 256, ROT_SMEM>>>(indices, codebook, norms);
    gemm_f16<<<dim3(NDIM / BN, BDIM / BM), 256, GEMM_SMEM>>>(out);
}

// round 17
// speedup vs baseline: 1.1942x; 1.1942x over previous
#include <cuda_runtime.h>
#include <cuda_fp16.h>
#include <cstdint>
#include <cstddef>

#define KDIM 4096
#define NDIM 4096
#define BDIM 8192
#define NG   32

// Scratch: rotated+scaled fp16 weights (32MB), fp16 X (64MB), k-major fp16 Pi (1MB).
__device__ __half g_Wh[(size_t)NDIM * KDIM];
__device__ __half g_Xh[(size_t)BDIM * KDIM];
__device__ __half g_PiTh[(size_t)NG * 128 * 128];

// ---------------------------------------------------------------------------
// Kernel 0: convert X to fp16.
// ---------------------------------------------------------------------------
__global__ void xhalf(const float4* __restrict__ x) {
    const size_t i = (size_t)blockIdx.x * blockDim.x + threadIdx.x;  // < B*K/4
    const float4 v = x[i];
    __half2 h01 = __floats2half2_rn(v.x, v.y);
    __half2 h23 = __floats2half2_rn(v.z, v.w);
    uint2 o;
    o.x = *(uint32_t*)&h01;
    o.y = *(uint32_t*)&h23;
    ((uint2*)g_Xh)[i] = o;
}

// ---------------------------------------------------------------------------
// Kernel 0b: PiTh[g][k][j] = fp16(rot[g][j][k]). One 32x32 tile per block.
// ---------------------------------------------------------------------------
__global__ void pit(const float* __restrict__ rot) {
    __shared__ float t[32][33];
    const int g = blockIdx.z;
    const int j0 = blockIdx.x * 32, k0 = blockIdx.y * 32;
    const int x = threadIdx.x, y = threadIdx.y;  // 32 x 8
    const float* src = rot + (size_t)g * 16384;
    __half* dst = g_PiTh + (size_t)g * 16384;
#pragma unroll
    for (int i = 0; i < 4; ++i)
        t[y + i * 8][x] = src[(j0 + y + i * 8) * 128 + k0 + x];
    __syncthreads();
#pragma unroll
    for (int i = 0; i < 4; ++i)
        dst[(size_t)(k0 + y + i * 8) * 128 + j0 + x] = __float2half_rn(t[x][y + i * 8]);
}

// ---------------------------------------------------------------------------
// Kernel 1: dequant + rotate on fp16 tensor cores.
// CTA (nblk, g): Wrot[128,128] = Wl_f16[128,128] @ PiTg^T via mma m16n8k16.
// Smem stride 136 halves (272B) -> conflict-free ldmatrix. No inner barriers.
// ---------------------------------------------------------------------------
#define RST 136                          // halves per smem row (272 B)
#define ROT_SMEM (2 * 128 * RST * 2)     // 69632 B -> 2 CTA/SM

static __device__ __forceinline__ void cp16(uint32_t dst, const void* src) {
    asm volatile("cp.async.cg.shared.global [%0], [%1], 16;\n" :: "r"(dst), "l"(src));
}

static __device__ __forceinline__ void ldm4(uint32_t* r, uint32_t addr) {
    asm volatile("ldmatrix.sync.aligned.m8n8.x4.shared.b16 {%0,%1,%2,%3}, [%4];"
                 : "=r"(r[0]), "=r"(r[1]), "=r"(r[2]), "=r"(r[3]) : "r"(addr));
}

static __device__ __forceinline__ void mma_f16(float* d, const uint32_t* a, const uint32_t* b) {
    asm volatile(
        "mma.sync.aligned.m16n8k16.row.col.f32.f16.f16.f32 "
        "{%0,%1,%2,%3}, {%4,%5,%6,%7}, {%8,%9}, {%0,%1,%2,%3};\n"
        : "+f"(d[0]), "+f"(d[1]), "+f"(d[2]), "+f"(d[3])
        : "r"(a[0]), "r"(a[1]), "r"(a[2]), "r"(a[3]), "r"(b[0]), "r"(b[1]));
}

__global__ __launch_bounds__(256, 2) void rotate_tc(const int* __restrict__ indices,
                                                    const float* __restrict__ codebook,
                                                    const float* __restrict__ norms) {
    extern __shared__ __half smh[];
    __half* Wls = smh;                 // 128 x RST (A operand: dequant weights)
    __half* Pis = smh + 128 * RST;     // 128 x RST (B operand: PiT rows, k-major)
    __shared__ float cb[16];
    __shared__ float nmv[128];
    const int tid = threadIdx.x;
    const int warp = tid >> 5, lane = tid & 31;
    const int g = blockIdx.y;
    const int n0 = blockIdx.x * 128;
    const uint32_t sWl = (uint32_t)__cvta_generic_to_shared(Wls);
    const uint32_t sPi = (uint32_t)__cvta_generic_to_shared(Pis);

    if (tid < 16) cb[tid] = codebook[tid];
    if (tid < 128) nmv[tid] = norms[(n0 + tid) * NG + g] * 0.088388347648318447f;
    __syncthreads();

    // Pi fill via cp.async (overlaps dequant LDGs below): 128 rows x 16 chunks.
    const __half* Pg = g_PiTh + (size_t)g * 16384;
#pragma unroll
    for (int p = 0; p < 8; ++p) {
        const int flat = p * 256 + tid;        // 0..2047
        const int row = flat >> 4;
        const int c = flat & 15;
        cp16(sPi + (uint32_t)(row * 272 + c * 16), Pg + row * 128 + c * 8);
    }
    asm volatile("cp.async.commit_group;\n");

    // Dequant 128x128 -> fp16 smem. Each thread: 8 chunks of 8 elems.
#pragma unroll
    for (int p = 0; p < 8; ++p) {
        const int flat8 = p * 256 + tid;       // 0..2047 (8-elem chunks)
        const int row = flat8 >> 4;            // 16 chunks per 128-elem row
        const int c8 = flat8 & 15;
        const int4 iv0 = *(const int4*)(indices + (size_t)(n0 + row) * KDIM + g * 128 + c8 * 8);
        const int4 iv1 = *(const int4*)(indices + (size_t)(n0 + row) * KDIM + g * 128 + c8 * 8 + 4);
        const float nm = nmv[row];
        __half2 h0 = __floats2half2_rn(cb[iv0.x] * nm, cb[iv0.y] * nm);
        __half2 h1 = __floats2half2_rn(cb[iv0.z] * nm, cb[iv0.w] * nm);
        __half2 h2 = __floats2half2_rn(cb[iv1.x] * nm, cb[iv1.y] * nm);
        __half2 h3 = __floats2half2_rn(cb[iv1.z] * nm, cb[iv1.w] * nm);
        uint4 o;
        o.x = *(uint32_t*)&h0; o.y = *(uint32_t*)&h1;
        o.z = *(uint32_t*)&h2; o.w = *(uint32_t*)&h3;
        asm volatile("st.shared.v4.b32 [%0], {%1,%2,%3,%4};" ::
                     "r"(sWl + (uint32_t)(row * 272 + c8 * 16)),
                     "r"(o.x), "r"(o.y), "r"(o.z), "r"(o.w));
    }
    asm volatile("cp.async.wait_group 0;\n");
    __syncthreads();

    // MMA: warp tile 64x32 over 128x128 output, j-inner 128 (8 k-steps).
    const int wm = (warp >> 2) * 64, wn = (warp & 3) * 32;
    const uint32_t aoff =
        (uint32_t)((((lane >> 3) & 1) * 8 + (lane & 7)) * 272 + (lane >> 4) * 16);
    const uint32_t boff =
        (uint32_t)(((lane >> 4) * 8 + (lane & 7)) * 272 + ((lane >> 3) & 1) * 16);
    const uint32_t At = sWl + (uint32_t)(wm * 272) + aoff;
    const uint32_t Bt = sPi + (uint32_t)(wn * 272) + boff;

    float acc[4][4][4];
#pragma unroll
    for (int i = 0; i < 4; ++i)
#pragma unroll
        for (int j = 0; j < 4; ++j)
#pragma unroll
            for (int r = 0; r < 4; ++r) acc[i][j][r] = 0.f;

#pragma unroll
    for (int ks = 0; ks < 8; ++ks) {
        uint32_t af[4][4], bf[4][2];
#pragma unroll
        for (int mt = 0; mt < 4; ++mt)
            ldm4(af[mt], At + (uint32_t)(mt * 16 * 272 + ks * 32));
#pragma unroll
        for (int np = 0; np < 2; ++np) {
            uint32_t r[4];
            ldm4(r, Bt + (uint32_t)(np * 16 * 272 + ks * 32));
            bf[np * 2][0] = r[0];
            bf[np * 2][1] = r[1];
            bf[np * 2 + 1][0] = r[2];
            bf[np * 2 + 1][1] = r[3];
        }
#pragma unroll
        for (int mt = 0; mt < 4; ++mt)
#pragma unroll
            for (int nt = 0; nt < 4; ++nt)
                mma_f16(acc[mt][nt], af[mt], bf[nt]);
    }

    // Epilogue: fp16 stores to g_Wh (row = N index, col = g*128 + kcol).
    const int lr = lane >> 2, lc = lane & 3;
#pragma unroll
    for (int mt = 0; mt < 4; ++mt) {
#pragma unroll
        for (int nt = 0; nt < 4; ++nt) {
            const int row = n0 + wm + mt * 16 + lr;
            const int col = g * 128 + wn + nt * 8 + lc * 2;
            __half2 h0 = __floats2half2_rn(acc[mt][nt][0], acc[mt][nt][1]);
            __half2 h1 = __floats2half2_rn(acc[mt][nt][2], acc[mt][nt][3]);
            *(__half2*)(g_Wh + (size_t)row * KDIM + col) = h0;
            *(__half2*)(g_Wh + (size_t)(row + 8) * KDIM + col) = h1;
        }
    }
}

// ---------------------------------------------------------------------------
// Kernel 2: out(8192x4096) = Xh @ Wh^T, fp16 mma.sync m16n8k16, fp32 acc.
// CTA 128x128, BK=64 halves, 3-stage cp.async, 8 warps (2x4), warp tile 64x32.
// (Exact R11/R13 kernel — best measured config.)
// ---------------------------------------------------------------------------
#define BM 128
#define BN 128
#define BK 64
#define STAGES 3
#define SSTRH 72                       // halves per row (144B)
#define A_H (BM * SSTRH)               // 9216 halves (18432B)
#define STG_B (2 * A_H * 2)            // 36864 bytes per stage (A+B)
#define GEMM_SMEM (STAGES * STG_B)     // 110592 B

static __device__ __forceinline__ void copy_stage(uint32_t sAu, int s,
                                                  const __half* __restrict__ Xh,
                                                  const __half* __restrict__ Wh,
                                                  int bm, int bn, int kt, int tid) {
    const int k0 = kt * BK;
    const uint32_t sbase = sAu + (uint32_t)(s * STG_B);
#pragma unroll
    for (int p = 0; p < 4; ++p) {
        const int a = p * 256 + tid;
        const int row = a >> 3;
        const int ck = a & 7;
        cp16(sbase + (uint32_t)(row * (SSTRH * 2) + ck * 16),
             Xh + (size_t)(bm + row) * KDIM + k0 + ck * 8);
    }
    const uint32_t bbase = sbase + (uint32_t)(A_H * 2);
#pragma unroll
    for (int p = 0; p < 4; ++p) {
        const int a = p * 256 + tid;
        const int row = a >> 3;
        const int ck = a & 7;
        cp16(bbase + (uint32_t)(row * (SSTRH * 2) + ck * 16),
             Wh + (size_t)(bn + row) * KDIM + k0 + ck * 8);
    }
}

__global__ __launch_bounds__(256, 2) void gemm_f16(float* __restrict__ out) {
    extern __shared__ __half smh[];
    const int tid = threadIdx.x;
    const int warp = tid >> 5, lane = tid & 31;
    const int wm = (warp >> 2) * 64, wn = (warp & 3) * 32;
    const int bm = blockIdx.y * BM, bn = blockIdx.x * BN;
    const __half* Xh = g_Xh;
    const __half* Wh = g_Wh;
    const uint32_t sAu = (uint32_t)__cvta_generic_to_shared(smh);

    float acc[4][4][4];
#pragma unroll
    for (int i = 0; i < 4; ++i)
#pragma unroll
        for (int j = 0; j < 4; ++j)
#pragma unroll
            for (int r = 0; r < 4; ++r) acc[i][j][r] = 0.f;

    const uint32_t aoff =
        (uint32_t)((((lane >> 3) & 1) * 8 + (lane & 7)) * 144 + (lane >> 4) * 16);
    const uint32_t boff =
        (uint32_t)(((lane >> 4) * 8 + (lane & 7)) * 144 + ((lane >> 3) & 1) * 16);

#pragma unroll
    for (int s = 0; s < STAGES - 1; ++s) {
        copy_stage(sAu, s, Xh, Wh, bm, bn, s, tid);
        asm volatile("cp.async.commit_group;\n");
    }
    asm volatile("cp.async.wait_group %0;\n" :: "n"(STAGES - 2));
    __syncthreads();

    const int lr = lane >> 2;
    const int lc = lane & 3;
    const int KT = KDIM / BK;  // 64
    int s_rd = 0, s_wr = STAGES - 1;

#pragma unroll 1
    for (int kt = 0; kt < KT; ++kt) {
        if (kt + STAGES - 1 < KT) {
            copy_stage(sAu, s_wr, Xh, Wh, bm, bn, kt + STAGES - 1, tid);
        }
        asm volatile("cp.async.commit_group;\n");

        const uint32_t At = sAu + (uint32_t)(s_rd * STG_B) + (uint32_t)(wm * 144) + aoff;
        const uint32_t Bt = sAu + (uint32_t)(s_rd * STG_B + A_H * 2) +
                            (uint32_t)(wn * 144) + boff;

#pragma unroll
        for (int ks = 0; ks < 4; ++ks) {
            uint32_t af[4][4], bf[4][2];
#pragma unroll
            for (int mt = 0; mt < 4; ++mt)
                ldm4(af[mt], At + (uint32_t)(mt * 16 * 144 + ks * 32));
#pragma unroll
            for (int np = 0; np < 2; ++np) {
                uint32_t r[4];
                ldm4(r, Bt + (uint32_t)(np * 16 * 144 + ks * 32));
                bf[np * 2][0] = r[0];
                bf[np * 2][1] = r[1];
                bf[np * 2 + 1][0] = r[2];
                bf[np * 2 + 1][1] = r[3];
            }
#pragma unroll
            for (int mt = 0; mt < 4; ++mt)
#pragma unroll
                for (int nt = 0; nt < 4; ++nt)
                    mma_f16(acc[mt][nt], af[mt], bf[nt]);
        }

        asm volatile("cp.async.wait_group %0;\n" :: "n"(STAGES - 2));
        __syncthreads();
        s_rd = (s_rd == STAGES - 1) ? 0 : s_rd + 1;
        s_wr = (s_wr == STAGES - 1) ? 0 : s_wr + 1;
    }

#pragma unroll
    for (int mt = 0; mt < 4; ++mt) {
#pragma unroll
        for (int nt = 0; nt < 4; ++nt) {
            const int row = bm + wm + mt * 16 + lr;
            const int col = bn + wn + nt * 8 + lc * 2;
            float2 v0 = make_float2(acc[mt][nt][0], acc[mt][nt][1]);
            float2 v1 = make_float2(acc[mt][nt][2], acc[mt][nt][3]);
            *(float2*)(out + (size_t)row * NDIM + col) = v0;
            *(float2*)(out + (size_t)(row + 8) * NDIM + col) = v1;
        }
    }
}

// ---------------------------------------------------------------------------
extern "C" void kernel_launch(void* const* d_in, const int* in_sizes, int n_in,
                              void* d_out, int out_size) {
    const float* x        = (const float*)d_in[0];   // (8192, 4096) f32
    const int*   indices  = (const int*)d_in[1];     // (4096, 4096) i32
    const float* codebook = (const float*)d_in[2];   // (16,) f32
    const float* norms    = (const float*)d_in[3];   // (4096, 32) f32
    const float* rot      = (const float*)d_in[4];   // (32, 128, 128) f32
    float* out = (float*)d_out;                      // (8192, 4096) f32

    cudaFuncSetAttribute(rotate_tc, cudaFuncAttributeMaxDynamicSharedMemorySize, ROT_SMEM);
    cudaFuncSetAttribute(gemm_f16, cudaFuncAttributeMaxDynamicSharedMemorySize, GEMM_SMEM);

    xhalf<<<(BDIM * KDIM / 4) / 256, 256>>>((const float4*)x);
    pit<<<dim3(4, 4, NG), dim3(32, 8)>>>(rot);
    rotate_tc<<<dim3(NDIM / 128, NG), 256, ROT_SMEM>>>(indices, codebook, norms);
    gemm_f16<<<dim3(NDIM / BN, BDIM / BM), 256, GEMM_SMEM>>>(out);
}